// round 3
// baseline (speedup 1.0000x reference)
#include <cuda_runtime.h>
#include <cuda_fp16.h>
#include <cstdint>

// ---------------------------------------------------------------------------
// Problem dims (fixed by the dataset)
// ---------------------------------------------------------------------------
#define NTOK 8192          // B*S tokens
#define DIM  1024          // model dim
#define HID  4096          // hidden dim
#define NE   8             // experts
#define CAP  8192          // per-expert token capacity (max possible)

#define BM 128
#define BN 128
#define BK 32
#define LDA (BK + 8)       // 40 halves  (80B rows, conflict-free for ldmatrix)
#define LDB (BN + 8)       // 136 halves (272B rows, conflict-free for ldmatrix)

// ---------------------------------------------------------------------------
// Scratch (static __device__ arrays; allocation-free kernel_launch)
// ---------------------------------------------------------------------------
__device__ int    g_cnt[NE];
__device__ int    g_ptok[NE * CAP];
__device__ float  g_pgate[NE * CAP];
__device__ __half g_X  [(size_t)NE * CAP * DIM];   // gathered tokens, fp16
__device__ __half g_W1h[(size_t)NE * DIM * HID];   // W1 fp16, layout [E][D][H]
__device__ __half g_W2h[(size_t)NE * HID * DIM];   // W2 fp16, layout [E][H][D]
__device__ __half g_Hb [(size_t)NE * CAP * HID];   // gelu(x@W1+b1), fp16

// ---------------------------------------------------------------------------
// PTX helpers (baseline compute_103-legal only: cp.async / ldmatrix / mma.sync)
// ---------------------------------------------------------------------------
__device__ __forceinline__ uint32_t smem_u32(const void* p) {
    uint32_t a;
    asm("{ .reg .u64 t; cvta.to.shared.u64 t, %1; cvt.u32.u64 %0, t; }"
        : "=r"(a) : "l"(p));
    return a;
}

__device__ __forceinline__ void cp16(uint32_t smaddr, const void* g) {
    asm volatile("cp.async.cg.shared.global [%0], [%1], 16;"
                 :: "r"(smaddr), "l"(g));
}
#define CP_COMMIT() asm volatile("cp.async.commit_group;" ::: "memory")
#define CP_WAIT(n)  asm volatile("cp.async.wait_group %0;" :: "n"(n) : "memory")

__device__ __forceinline__ void ldsm_x4(uint32_t* r, uint32_t addr) {
    asm volatile("ldmatrix.sync.aligned.m8n8.x4.shared.b16 {%0,%1,%2,%3}, [%4];"
                 : "=r"(r[0]), "=r"(r[1]), "=r"(r[2]), "=r"(r[3]) : "r"(addr));
}
__device__ __forceinline__ void ldsm_x4_t(uint32_t* r, uint32_t addr) {
    asm volatile("ldmatrix.sync.aligned.m8n8.x4.trans.shared.b16 {%0,%1,%2,%3}, [%4];"
                 : "=r"(r[0]), "=r"(r[1]), "=r"(r[2]), "=r"(r[3]) : "r"(addr));
}

__device__ __forceinline__ void mma16816(float* c, const uint32_t* a, const uint32_t* b) {
    asm volatile(
        "mma.sync.aligned.m16n8k16.row.col.f32.f16.f16.f32 "
        "{%0,%1,%2,%3}, {%4,%5,%6,%7}, {%8,%9}, {%0,%1,%2,%3};"
        : "+f"(c[0]), "+f"(c[1]), "+f"(c[2]), "+f"(c[3])
        : "r"(a[0]), "r"(a[1]), "r"(a[2]), "r"(a[3]), "r"(b[0]), "r"(b[1]));
}

// tanh-approximate GELU (JAX default): x * sigmoid(2u), u = 0.79788(x+0.044715x^3)
__device__ __forceinline__ float gelu_f(float v) {
    float u2 = 2.0f * 0.7978845608028654f * (v + 0.044715f * v * v * v);
    u2 = fminf(fmaxf(u2, -30.0f), 30.0f);
    float t = __expf(u2);
    return v * __fdividef(t, t + 1.0f);
}

// ---------------------------------------------------------------------------
// Kernel 1: zero output + counters
// ---------------------------------------------------------------------------
__global__ void zero_kernel(float* __restrict__ out, size_t n4) {
    size_t i = (size_t)blockIdx.x * blockDim.x + threadIdx.x;
    float4 z = make_float4(0.f, 0.f, 0.f, 0.f);
    size_t stride = (size_t)gridDim.x * blockDim.x;
    for (; i < n4; i += stride) ((float4*)out)[i] = z;
    if (blockIdx.x == 0 && threadIdx.x < NE) g_cnt[threadIdx.x] = 0;
}

// ---------------------------------------------------------------------------
// Kernel 2: router — one warp per token
// ---------------------------------------------------------------------------
__global__ void router_kernel(const float* __restrict__ x,
                              const float* __restrict__ Wr) {
    int gwarp = (blockIdx.x * blockDim.x + threadIdx.x) >> 5;
    int lane = threadIdx.x & 31;
    if (gwarp >= NTOK) return;
    const float* xr = x + (size_t)gwarp * DIM;
    float a0 = 0, a1 = 0, a2 = 0, a3 = 0, a4 = 0, a5 = 0, a6 = 0, a7 = 0;
    for (int d = lane; d < DIM; d += 32) {
        float xv = xr[d];
        const float4* w = (const float4*)(Wr + (size_t)d * NE);
        float4 w0 = w[0], w1 = w[1];
        a0 += xv * w0.x; a1 += xv * w0.y; a2 += xv * w0.z; a3 += xv * w0.w;
        a4 += xv * w1.x; a5 += xv * w1.y; a6 += xv * w1.z; a7 += xv * w1.w;
    }
#pragma unroll
    for (int o = 16; o > 0; o >>= 1) {
        a0 += __shfl_xor_sync(0xffffffffu, a0, o);
        a1 += __shfl_xor_sync(0xffffffffu, a1, o);
        a2 += __shfl_xor_sync(0xffffffffu, a2, o);
        a3 += __shfl_xor_sync(0xffffffffu, a3, o);
        a4 += __shfl_xor_sync(0xffffffffu, a4, o);
        a5 += __shfl_xor_sync(0xffffffffu, a5, o);
        a6 += __shfl_xor_sync(0xffffffffu, a6, o);
        a7 += __shfl_xor_sync(0xffffffffu, a7, o);
    }
    if (lane == 0) {
        float p[8] = {a0, a1, a2, a3, a4, a5, a6, a7};
        float m = p[0];
#pragma unroll
        for (int e = 1; e < 8; e++) m = fmaxf(m, p[e]);
        float s = 0.f;
#pragma unroll
        for (int e = 0; e < 8; e++) { p[e] = expf(p[e] - m); s += p[e]; }
        float inv = 1.0f / s;
#pragma unroll
        for (int e = 0; e < 8; e++) p[e] *= inv;
        int i1 = 0; float v1 = p[0];
#pragma unroll
        for (int e = 1; e < 8; e++) if (p[e] > v1) { v1 = p[e]; i1 = e; }
        int i2 = -1; float v2 = -1.0f;
#pragma unroll
        for (int e = 0; e < 8; e++)
            if (e != i1 && p[e] > v2) { v2 = p[e]; i2 = e; }
        int s1 = atomicAdd(&g_cnt[i1], 1);
        g_ptok[i1 * CAP + s1] = gwarp; g_pgate[i1 * CAP + s1] = v1;
        int s2 = atomicAdd(&g_cnt[i2], 1);
        g_ptok[i2 * CAP + s2] = gwarp; g_pgate[i2 * CAP + s2] = v2;
    }
}

// ---------------------------------------------------------------------------
// Kernel 3: gather tokens -> fp16 per-expert buffer
// ---------------------------------------------------------------------------
__global__ void gather_kernel(const float* __restrict__ x) {
    int e = blockIdx.y, slot = blockIdx.x;
    if (slot >= g_cnt[e]) return;
    int t = g_ptok[e * CAP + slot];
    const float4* src = (const float4*)(x + (size_t)t * DIM);
    uint2* dst = (uint2*)(g_X + ((size_t)e * CAP + slot) * DIM);
    int i = threadIdx.x;                 // 256 threads * 4 floats = 1024
    float4 v = src[i];
    __half2 h0 = __floats2half2_rn(v.x, v.y);
    __half2 h1 = __floats2half2_rn(v.z, v.w);
    uint2 u;
    u.x = *reinterpret_cast<unsigned*>(&h0);
    u.y = *reinterpret_cast<unsigned*>(&h1);
    dst[i] = u;
}

// ---------------------------------------------------------------------------
// Kernel 4: fp32 -> fp16 weight convert (no transpose: ldmatrix.trans consumes
// native [K,N] layout). Converts both W1 and W2 (same element count).
// ---------------------------------------------------------------------------
__global__ void convert_w_kernel(const float* __restrict__ W1,
                                 const float* __restrict__ W2) {
    size_t n4 = (size_t)NE * DIM * HID / 4;
    size_t stride = (size_t)gridDim.x * blockDim.x;
    for (size_t i = (size_t)blockIdx.x * blockDim.x + threadIdx.x; i < n4; i += stride) {
        float4 v1 = ((const float4*)W1)[i];
        float4 v2 = ((const float4*)W2)[i];
        __half2 a0 = __floats2half2_rn(v1.x, v1.y);
        __half2 a1 = __floats2half2_rn(v1.z, v1.w);
        __half2 b0 = __floats2half2_rn(v2.x, v2.y);
        __half2 b1 = __floats2half2_rn(v2.z, v2.w);
        uint2 u1, u2;
        u1.x = *reinterpret_cast<unsigned*>(&a0);
        u1.y = *reinterpret_cast<unsigned*>(&a1);
        u2.x = *reinterpret_cast<unsigned*>(&b0);
        u2.y = *reinterpret_cast<unsigned*>(&b1);
        ((uint2*)g_W1h)[i] = u1;
        ((uint2*)g_W2h)[i] = u2;
    }
}

// ---------------------------------------------------------------------------
// Kernel 5: fp16 mma.sync GEMM, 128x128x32 tiles, 2-stage cp.async pipeline
// mode 0: H = gelu(X @ W1 + b1)        (A = g_X [rows,D], B = W1h [D,H])
// mode 1: out[tok] += gate*(H @ W2+b2) (A = g_Hb [rows,H], B = W2h [H,D])
// 8 warps as 4(M) x 2(N); warp tile 32x64; mma m16n8k16.
// ---------------------------------------------------------------------------
struct GSmem {
    __half A[2][BM][LDA];
    __half B[2][BK][LDB];
};

__global__ void __launch_bounds__(256, 2)
moe_gemm_kernel(int mode, const float* __restrict__ bias, float* __restrict__ out) {
    __shared__ GSmem sm;
    int e = blockIdx.z;
    int cnt = g_cnt[e];
    int row0 = blockIdx.y * BM;
    if (row0 >= cnt) return;
    int valid = cnt - row0;          // rows alive in this tile (may exceed BM)
    int nb0 = blockIdx.x * BN;

    const __half* Ag; const __half* Bg;
    int lda, ldb, Kdim;
    if (mode == 0) {
        Ag = g_X   + (size_t)e * CAP * DIM + (size_t)row0 * DIM;  lda = DIM;
        Bg = g_W1h + (size_t)e * DIM * HID;                       ldb = HID;
        Kdim = DIM;
    } else {
        Ag = g_Hb  + (size_t)e * CAP * HID + (size_t)row0 * HID;  lda = HID;
        Bg = g_W2h + (size_t)e * HID * DIM;                       ldb = DIM;
        Kdim = HID;
    }

    int tid = threadIdx.x;
    int lane = tid & 31;
    int warp = tid >> 5;
    int wm = warp >> 1;              // 0..3  (M groups of 32)
    int wn = warp & 1;               // 0..1  (N groups of 64)

    float acc[2][8][4];
#pragma unroll
    for (int mi = 0; mi < 2; mi++)
#pragma unroll
        for (int nj = 0; nj < 8; nj++)
#pragma unroll
            for (int q = 0; q < 4; q++) acc[mi][nj][q] = 0.f;

    // --- cp.async stage loader: A tile 128x32 (512 x 16B), B tile 32x128 (512 x 16B)
    auto load_stage = [&](int kt, int s) {
#pragma unroll
        for (int i = 0; i < 2; i++) {
            int c = tid + i * 256;
            int r = c >> 2, cc = c & 3;
            cp16(smem_u32(&sm.A[s][r][cc * 8]),
                 Ag + (size_t)r * lda + kt * BK + cc * 8);
        }
#pragma unroll
        for (int i = 0; i < 2; i++) {
            int c = tid + i * 256;
            int r = c >> 4, cc = c & 15;
            cp16(smem_u32(&sm.B[s][r][cc * 8]),
                 Bg + (size_t)(kt * BK + r) * ldb + nb0 + cc * 8);
        }
        CP_COMMIT();
    };

    int nk = Kdim / BK;
    load_stage(0, 0);

    for (int kt = 0; kt < nk; kt++) {
        int cur = kt & 1;
        if (kt + 1 < nk) { load_stage(kt + 1, cur ^ 1); CP_WAIT(1); }
        else             { CP_WAIT(0); }
        __syncthreads();

#pragma unroll
        for (int ks = 0; ks < 2; ks++) {
            uint32_t af[2][4];
#pragma unroll
            for (int mi = 0; mi < 2; mi++) {
                int r = wm * 32 + mi * 16 + (lane & 15);
                int cc = ks * 16 + ((lane >> 4) << 3);
                ldsm_x4(af[mi], smem_u32(&sm.A[cur][r][cc]));
            }
            uint32_t bf[8][2];
#pragma unroll
            for (int j = 0; j < 4; j++) {
                int kr = ks * 16 + (lane & 7) + (((lane >> 3) & 1) << 3);
                int nc = wn * 64 + j * 16 + ((lane >> 4) << 3);
                uint32_t r4[4];
                ldsm_x4_t(r4, smem_u32(&sm.B[cur][kr][nc]));
                bf[2 * j][0] = r4[0]; bf[2 * j][1] = r4[1];
                bf[2 * j + 1][0] = r4[2]; bf[2 * j + 1][1] = r4[3];
            }
#pragma unroll
            for (int mi = 0; mi < 2; mi++)
#pragma unroll
                for (int nj = 0; nj < 8; nj++)
                    mma16816(acc[mi][nj], af[mi], bf[nj]);
        }
        __syncthreads();
    }

    // --- Epilogue. acc[mi][nj]: rows wm*32+mi*16+{lane/4, +8}, cols wn*64+nj*8+(lane%4)*2+{0,1}
    if (mode == 0) {
        const float* bp = bias + (size_t)e * HID + nb0;
#pragma unroll
        for (int mi = 0; mi < 2; mi++) {
            int rb = wm * 32 + mi * 16 + (lane >> 2);
#pragma unroll
            for (int hr = 0; hr < 2; hr++) {
                int r = rb + hr * 8;
                if (r < valid) {
                    size_t rowoff = ((size_t)e * CAP + row0 + r) * HID + nb0;
#pragma unroll
                    for (int nj = 0; nj < 8; nj++) {
                        int colc = wn * 64 + nj * 8 + ((lane & 3) << 1);
                        float v0 = acc[mi][nj][hr * 2 + 0] + bp[colc];
                        float v1 = acc[mi][nj][hr * 2 + 1] + bp[colc + 1];
                        __half2 h2 = __floats2half2_rn(gelu_f(v0), gelu_f(v1));
                        *(__half2*)(g_Hb + rowoff + colc) = h2;
                    }
                }
            }
        }
    } else {
        const float* bp = bias + (size_t)e * DIM + nb0;
#pragma unroll
        for (int mi = 0; mi < 2; mi++) {
            int rb = wm * 32 + mi * 16 + (lane >> 2);
#pragma unroll
            for (int hr = 0; hr < 2; hr++) {
                int r = rb + hr * 8;
                if (r < valid) {
                    int t = g_ptok[e * CAP + row0 + r];
                    float gate = g_pgate[e * CAP + row0 + r];
                    float* orow = out + (size_t)t * DIM + nb0;
#pragma unroll
                    for (int nj = 0; nj < 8; nj++) {
                        int colc = wn * 64 + nj * 8 + ((lane & 3) << 1);
                        float v0 = acc[mi][nj][hr * 2 + 0] + bp[colc];
                        float v1 = acc[mi][nj][hr * 2 + 1] + bp[colc + 1];
                        atomicAdd(orow + colc,     gate * v0);
                        atomicAdd(orow + colc + 1, gate * v1);
                    }
                }
            }
        }
    }
}

// ---------------------------------------------------------------------------
// Launch
// ---------------------------------------------------------------------------
extern "C" void kernel_launch(void* const* d_in, const int* in_sizes, int n_in,
                              void* d_out, int out_size) {
    const float* x  = (const float*)d_in[0];
    const float* Wr = (const float*)d_in[1];
    const float* W1 = (const float*)d_in[2];
    const float* b1 = (const float*)d_in[3];
    const float* W2 = (const float*)d_in[4];
    const float* b2 = (const float*)d_in[5];
    float* out = (float*)d_out;

    // 1. zero output + expert counters
    zero_kernel<<<2048, 256>>>(out, (size_t)NTOK * DIM / 4);
    // 2. router (one warp per token)
    router_kernel<<<NTOK / 8, 256>>>(x, Wr);
    // 3. gather tokens into per-expert fp16 buffers
    gather_kernel<<<dim3(CAP, NE), 256>>>(x);
    // 4. fp32 -> fp16 weight conversion (no transpose needed)
    convert_w_kernel<<<2048, 256>>>(W1, W2);
    // 5. GEMM1: H = gelu(X @ W1 + b1)
    moe_gemm_kernel<<<dim3(HID / BN, CAP / BM, NE), 256>>>(0, b1, nullptr);
    // 6. GEMM2: out += gate * (H @ W2 + b2)
    moe_gemm_kernel<<<dim3(DIM / BN, CAP / BM, NE), 256>>>(1, b2, out);
}

// round 4
// speedup vs baseline: 1.0367x; 1.0367x over previous
#include <cuda_runtime.h>
#include <cuda_fp16.h>
#include <cstdint>

// ---------------------------------------------------------------------------
// Problem dims (fixed by the dataset)
// ---------------------------------------------------------------------------
#define NTOK 8192          // B*S tokens
#define DIM  1024          // model dim
#define HID  4096          // hidden dim
#define NE   8             // experts
#define CAP  8192          // per-expert token capacity (max possible)

#define BM 128
#define BN 128
#define BK 32
#define ST 4               // cp.async pipeline stages
#define LDA (BK + 8)       // 40 halves  (80B rows, conflict-free for ldmatrix)
#define LDB (BN + 8)       // 136 halves (272B rows, conflict-free for ldmatrix)

// ---------------------------------------------------------------------------
// Scratch (static __device__ arrays; allocation-free kernel_launch)
// ---------------------------------------------------------------------------
__device__ int    g_cnt[NE];
__device__ int    g_ptok[NE * CAP];
__device__ float  g_pgate[NE * CAP];
__device__ __half g_X  [(size_t)NE * CAP * DIM];   // gathered tokens, fp16
__device__ __half g_W1h[(size_t)NE * DIM * HID];   // W1 fp16, layout [E][D][H]
__device__ __half g_W2h[(size_t)NE * HID * DIM];   // W2 fp16, layout [E][H][D]
__device__ __half g_Hb [(size_t)NE * CAP * HID];   // gelu(x@W1+b1), fp16

// ---------------------------------------------------------------------------
// PTX helpers (baseline compute_103-legal only: cp.async / ldmatrix / mma.sync)
// ---------------------------------------------------------------------------
__device__ __forceinline__ uint32_t smem_u32(const void* p) {
    uint32_t a;
    asm("{ .reg .u64 t; cvta.to.shared.u64 t, %1; cvt.u32.u64 %0, t; }"
        : "=r"(a) : "l"(p));
    return a;
}

__device__ __forceinline__ void cp16(uint32_t smaddr, const void* g) {
    asm volatile("cp.async.cg.shared.global [%0], [%1], 16;"
                 :: "r"(smaddr), "l"(g));
}
#define CP_COMMIT() asm volatile("cp.async.commit_group;" ::: "memory")
#define CP_WAIT(n)  asm volatile("cp.async.wait_group %0;" :: "n"(n) : "memory")

__device__ __forceinline__ void ldsm_x4(uint32_t* r, uint32_t addr) {
    asm volatile("ldmatrix.sync.aligned.m8n8.x4.shared.b16 {%0,%1,%2,%3}, [%4];"
                 : "=r"(r[0]), "=r"(r[1]), "=r"(r[2]), "=r"(r[3]) : "r"(addr));
}
__device__ __forceinline__ void ldsm_x4_t(uint32_t* r, uint32_t addr) {
    asm volatile("ldmatrix.sync.aligned.m8n8.x4.trans.shared.b16 {%0,%1,%2,%3}, [%4];"
                 : "=r"(r[0]), "=r"(r[1]), "=r"(r[2]), "=r"(r[3]) : "r"(addr));
}

__device__ __forceinline__ void mma16816(float* c, const uint32_t* a, const uint32_t* b) {
    asm volatile(
        "mma.sync.aligned.m16n8k16.row.col.f32.f16.f16.f32 "
        "{%0,%1,%2,%3}, {%4,%5,%6,%7}, {%8,%9}, {%0,%1,%2,%3};"
        : "+f"(c[0]), "+f"(c[1]), "+f"(c[2]), "+f"(c[3])
        : "r"(a[0]), "r"(a[1]), "r"(a[2]), "r"(a[3]), "r"(b[0]), "r"(b[1]));
}

// tanh-approximate GELU (JAX default): x * sigmoid(2u), u = 0.79788(x+0.044715x^3)
__device__ __forceinline__ float gelu_f(float v) {
    float u2 = 2.0f * 0.7978845608028654f * (v + 0.044715f * v * v * v);
    u2 = fminf(fmaxf(u2, -30.0f), 30.0f);
    float t = __expf(u2);
    return v * __fdividef(t, t + 1.0f);
}

// ---------------------------------------------------------------------------
// Kernel 1: zero output + counters
// ---------------------------------------------------------------------------
__global__ void zero_kernel(float* __restrict__ out, size_t n4) {
    size_t i = (size_t)blockIdx.x * blockDim.x + threadIdx.x;
    float4 z = make_float4(0.f, 0.f, 0.f, 0.f);
    size_t stride = (size_t)gridDim.x * blockDim.x;
    for (; i < n4; i += stride) ((float4*)out)[i] = z;
    if (blockIdx.x == 0 && threadIdx.x < NE) g_cnt[threadIdx.x] = 0;
}

// ---------------------------------------------------------------------------
// Kernel 2: router — one warp per token
// ---------------------------------------------------------------------------
__global__ void router_kernel(const float* __restrict__ x,
                              const float* __restrict__ Wr) {
    int gwarp = (blockIdx.x * blockDim.x + threadIdx.x) >> 5;
    int lane = threadIdx.x & 31;
    if (gwarp >= NTOK) return;
    const float* xr = x + (size_t)gwarp * DIM;
    float a0 = 0, a1 = 0, a2 = 0, a3 = 0, a4 = 0, a5 = 0, a6 = 0, a7 = 0;
    for (int d = lane; d < DIM; d += 32) {
        float xv = xr[d];
        const float4* w = (const float4*)(Wr + (size_t)d * NE);
        float4 w0 = w[0], w1 = w[1];
        a0 += xv * w0.x; a1 += xv * w0.y; a2 += xv * w0.z; a3 += xv * w0.w;
        a4 += xv * w1.x; a5 += xv * w1.y; a6 += xv * w1.z; a7 += xv * w1.w;
    }
#pragma unroll
    for (int o = 16; o > 0; o >>= 1) {
        a0 += __shfl_xor_sync(0xffffffffu, a0, o);
        a1 += __shfl_xor_sync(0xffffffffu, a1, o);
        a2 += __shfl_xor_sync(0xffffffffu, a2, o);
        a3 += __shfl_xor_sync(0xffffffffu, a3, o);
        a4 += __shfl_xor_sync(0xffffffffu, a4, o);
        a5 += __shfl_xor_sync(0xffffffffu, a5, o);
        a6 += __shfl_xor_sync(0xffffffffu, a6, o);
        a7 += __shfl_xor_sync(0xffffffffu, a7, o);
    }
    if (lane == 0) {
        float p[8] = {a0, a1, a2, a3, a4, a5, a6, a7};
        float m = p[0];
#pragma unroll
        for (int e = 1; e < 8; e++) m = fmaxf(m, p[e]);
        float s = 0.f;
#pragma unroll
        for (int e = 0; e < 8; e++) { p[e] = expf(p[e] - m); s += p[e]; }
        float inv = 1.0f / s;
#pragma unroll
        for (int e = 0; e < 8; e++) p[e] *= inv;
        int i1 = 0; float v1 = p[0];
#pragma unroll
        for (int e = 1; e < 8; e++) if (p[e] > v1) { v1 = p[e]; i1 = e; }
        int i2 = -1; float v2 = -1.0f;
#pragma unroll
        for (int e = 0; e < 8; e++)
            if (e != i1 && p[e] > v2) { v2 = p[e]; i2 = e; }
        int s1 = atomicAdd(&g_cnt[i1], 1);
        g_ptok[i1 * CAP + s1] = gwarp; g_pgate[i1 * CAP + s1] = v1;
        int s2 = atomicAdd(&g_cnt[i2], 1);
        g_ptok[i2 * CAP + s2] = gwarp; g_pgate[i2 * CAP + s2] = v2;
    }
}

// ---------------------------------------------------------------------------
// Kernel 3: gather tokens -> fp16 per-expert buffer
// ---------------------------------------------------------------------------
__global__ void gather_kernel(const float* __restrict__ x) {
    int e = blockIdx.y, slot = blockIdx.x;
    if (slot >= g_cnt[e]) return;
    int t = g_ptok[e * CAP + slot];
    const float4* src = (const float4*)(x + (size_t)t * DIM);
    uint2* dst = (uint2*)(g_X + ((size_t)e * CAP + slot) * DIM);
    int i = threadIdx.x;                 // 256 threads * 4 floats = 1024
    float4 v = src[i];
    __half2 h0 = __floats2half2_rn(v.x, v.y);
    __half2 h1 = __floats2half2_rn(v.z, v.w);
    uint2 u;
    u.x = *reinterpret_cast<unsigned*>(&h0);
    u.y = *reinterpret_cast<unsigned*>(&h1);
    dst[i] = u;
}

// ---------------------------------------------------------------------------
// Kernel 4: fp32 -> fp16 weight convert (no transpose: ldmatrix.trans consumes
// native [K,N] layout). Converts both W1 and W2 (same element count).
// ---------------------------------------------------------------------------
__global__ void convert_w_kernel(const float* __restrict__ W1,
                                 const float* __restrict__ W2) {
    size_t n4 = (size_t)NE * DIM * HID / 4;
    size_t stride = (size_t)gridDim.x * blockDim.x;
    for (size_t i = (size_t)blockIdx.x * blockDim.x + threadIdx.x; i < n4; i += stride) {
        float4 v1 = ((const float4*)W1)[i];
        float4 v2 = ((const float4*)W2)[i];
        __half2 a0 = __floats2half2_rn(v1.x, v1.y);
        __half2 a1 = __floats2half2_rn(v1.z, v1.w);
        __half2 b0 = __floats2half2_rn(v2.x, v2.y);
        __half2 b1 = __floats2half2_rn(v2.z, v2.w);
        uint2 u1, u2;
        u1.x = *reinterpret_cast<unsigned*>(&a0);
        u1.y = *reinterpret_cast<unsigned*>(&a1);
        u2.x = *reinterpret_cast<unsigned*>(&b0);
        u2.y = *reinterpret_cast<unsigned*>(&b1);
        ((uint2*)g_W1h)[i] = u1;
        ((uint2*)g_W2h)[i] = u2;
    }
}

// ---------------------------------------------------------------------------
// Kernel 5: fp16 mma.sync GEMM, 128x128x32 tiles, 4-stage cp.async pipeline,
// single __syncthreads per K-iteration.
// mode 0: H = gelu(X @ W1 + b1)        (A = g_X [rows,D], B = W1h [D,H])
// mode 1: out[tok] += gate*(H @ W2+b2) (A = g_Hb [rows,H], B = W2h [H,D])
// 8 warps as 4(M) x 2(N); warp tile 32x64; mma m16n8k16.
// ---------------------------------------------------------------------------
struct GSmem {
    __half A[ST][BM][LDA];   // 4 * 128*40*2 = 40960 B
    __half B[ST][BK][LDB];   // 4 * 32*136*2 = 34816 B
};
#define GSMEM_BYTES ((int)sizeof(GSmem))   // 75776 B

__global__ void __launch_bounds__(256, 2)
moe_gemm_kernel(int mode, const float* __restrict__ bias, float* __restrict__ out) {
    extern __shared__ char dyn_smem[];
    GSmem& sm = *reinterpret_cast<GSmem*>(dyn_smem);

    int e = blockIdx.z;
    int cnt = g_cnt[e];
    int row0 = blockIdx.y * BM;
    if (row0 >= cnt) return;
    int valid = cnt - row0;          // rows alive in this tile (may exceed BM)
    int nb0 = blockIdx.x * BN;

    const __half* Ag; const __half* Bg;
    int lda, ldb, Kdim;
    if (mode == 0) {
        Ag = g_X   + (size_t)e * CAP * DIM + (size_t)row0 * DIM;  lda = DIM;
        Bg = g_W1h + (size_t)e * DIM * HID;                       ldb = HID;
        Kdim = DIM;
    } else {
        Ag = g_Hb  + (size_t)e * CAP * HID + (size_t)row0 * HID;  lda = HID;
        Bg = g_W2h + (size_t)e * HID * DIM;                       ldb = DIM;
        Kdim = HID;
    }

    int tid = threadIdx.x;
    int lane = tid & 31;
    int warp = tid >> 5;
    int wm = warp >> 1;              // 0..3  (M groups of 32)
    int wn = warp & 1;               // 0..1  (N groups of 64)

    float acc[2][8][4];
#pragma unroll
    for (int mi = 0; mi < 2; mi++)
#pragma unroll
        for (int nj = 0; nj < 8; nj++)
#pragma unroll
            for (int q = 0; q < 4; q++) acc[mi][nj][q] = 0.f;

    // --- cp.async stage loader: A tile 128x32 (512 x 16B), B tile 32x128 (512 x 16B)
    auto load_stage = [&](int kt, int s) {
#pragma unroll
        for (int i = 0; i < 2; i++) {
            int c = tid + i * 256;
            int r = c >> 2, cc = c & 3;
            cp16(smem_u32(&sm.A[s][r][cc * 8]),
                 Ag + (size_t)r * lda + kt * BK + cc * 8);
        }
#pragma unroll
        for (int i = 0; i < 2; i++) {
            int c = tid + i * 256;
            int r = c >> 4, cc = c & 15;
            cp16(smem_u32(&sm.B[s][r][cc * 8]),
                 Bg + (size_t)(kt * BK + r) * ldb + nb0 + cc * 8);
        }
        CP_COMMIT();
    };

    int nk = Kdim / BK;              // 32 (GEMM1) or 128 (GEMM2); always > ST
    // prologue: fill ST-1 stages (3 groups in flight)
#pragma unroll
    for (int p = 0; p < ST - 1; p++) load_stage(p, p);

    for (int kt = 0; kt < nk; kt++) {
        CP_WAIT(ST - 2);             // <=2 groups pending -> stage kt resident
        __syncthreads();             // also proves stage (kt-1) fully consumed
        if (kt + ST - 1 < nk) load_stage(kt + ST - 1, (kt + ST - 1) % ST);
        else                  CP_COMMIT();   // empty group keeps wait invariant
        int cur = kt % ST;

#pragma unroll
        for (int ks = 0; ks < 2; ks++) {
            uint32_t af[2][4];
#pragma unroll
            for (int mi = 0; mi < 2; mi++) {
                int r = wm * 32 + mi * 16 + (lane & 15);
                int cc = ks * 16 + ((lane >> 4) << 3);
                ldsm_x4(af[mi], smem_u32(&sm.A[cur][r][cc]));
            }
            uint32_t bf[8][2];
#pragma unroll
            for (int j = 0; j < 4; j++) {
                int kr = ks * 16 + (lane & 7) + (((lane >> 3) & 1) << 3);
                int nc = wn * 64 + j * 16 + ((lane >> 4) << 3);
                uint32_t r4[4];
                ldsm_x4_t(r4, smem_u32(&sm.B[cur][kr][nc]));
                bf[2 * j][0] = r4[0]; bf[2 * j][1] = r4[1];
                bf[2 * j + 1][0] = r4[2]; bf[2 * j + 1][1] = r4[3];
            }
#pragma unroll
            for (int mi = 0; mi < 2; mi++)
#pragma unroll
                for (int nj = 0; nj < 8; nj++)
                    mma16816(acc[mi][nj], af[mi], bf[nj]);
        }
    }

    // --- Epilogue. acc[mi][nj]: rows wm*32+mi*16+{lane/4, +8}, cols wn*64+nj*8+(lane%4)*2+{0,1}
    if (mode == 0) {
        const float* bp = bias + (size_t)e * HID + nb0;
#pragma unroll
        for (int mi = 0; mi < 2; mi++) {
            int rb = wm * 32 + mi * 16 + (lane >> 2);
#pragma unroll
            for (int hr = 0; hr < 2; hr++) {
                int r = rb + hr * 8;
                if (r < valid) {
                    size_t rowoff = ((size_t)e * CAP + row0 + r) * HID + nb0;
#pragma unroll
                    for (int nj = 0; nj < 8; nj++) {
                        int colc = wn * 64 + nj * 8 + ((lane & 3) << 1);
                        float v0 = acc[mi][nj][hr * 2 + 0] + bp[colc];
                        float v1 = acc[mi][nj][hr * 2 + 1] + bp[colc + 1];
                        __half2 h2 = __floats2half2_rn(gelu_f(v0), gelu_f(v1));
                        *(__half2*)(g_Hb + rowoff + colc) = h2;
                    }
                }
            }
        }
    } else {
        const float* bp = bias + (size_t)e * DIM + nb0;
#pragma unroll
        for (int mi = 0; mi < 2; mi++) {
            int rb = wm * 32 + mi * 16 + (lane >> 2);
#pragma unroll
            for (int hr = 0; hr < 2; hr++) {
                int r = rb + hr * 8;
                if (r < valid) {
                    int t = g_ptok[e * CAP + row0 + r];
                    float gate = g_pgate[e * CAP + row0 + r];
                    float* orow = out + (size_t)t * DIM + nb0;
#pragma unroll
                    for (int nj = 0; nj < 8; nj++) {
                        int colc = wn * 64 + nj * 8 + ((lane & 3) << 1);
                        float v0 = acc[mi][nj][hr * 2 + 0] + bp[colc];
                        float v1 = acc[mi][nj][hr * 2 + 1] + bp[colc + 1];
                        atomicAdd(orow + colc,     gate * v0);
                        atomicAdd(orow + colc + 1, gate * v1);
                    }
                }
            }
        }
    }
}

// ---------------------------------------------------------------------------
// Launch
// ---------------------------------------------------------------------------
extern "C" void kernel_launch(void* const* d_in, const int* in_sizes, int n_in,
                              void* d_out, int out_size) {
    const float* x  = (const float*)d_in[0];
    const float* Wr = (const float*)d_in[1];
    const float* W1 = (const float*)d_in[2];
    const float* b1 = (const float*)d_in[3];
    const float* W2 = (const float*)d_in[4];
    const float* b2 = (const float*)d_in[5];
    float* out = (float*)d_out;

    static int smem_set = 0;
    if (!smem_set) {
        cudaFuncSetAttribute(moe_gemm_kernel,
                             cudaFuncAttributeMaxDynamicSharedMemorySize,
                             GSMEM_BYTES);
        smem_set = 1;
    }

    // 1. zero output + expert counters
    zero_kernel<<<2048, 256>>>(out, (size_t)NTOK * DIM / 4);
    // 2. router (one warp per token)
    router_kernel<<<NTOK / 8, 256>>>(x, Wr);
    // 3. gather tokens into per-expert fp16 buffers
    gather_kernel<<<dim3(CAP, NE), 256>>>(x);
    // 4. fp32 -> fp16 weight conversion (no transpose needed)
    convert_w_kernel<<<2048, 256>>>(W1, W2);
    // 5. GEMM1: H = gelu(X @ W1 + b1)
    moe_gemm_kernel<<<dim3(HID / BN, CAP / BM, NE), 256, GSMEM_BYTES>>>(0, b1, nullptr);
    // 6. GEMM2: out += gate * (H @ W2 + b2)
    moe_gemm_kernel<<<dim3(DIM / BN, CAP / BM, NE), 256, GSMEM_BYTES>>>(1, b2, out);
}